// round 11
// baseline (speedup 1.0000x reference)
#include <cuda_runtime.h>
#include <cuda_fp16.h>
#include <cstdint>

// ---------------------------------------------------------------------------
// GATNet 2-layer GAT, N=50000, E=800000 (+self loops).
// GEMM1 = 3xTF32 tensor-core (128x64 tile) with fused attention logits.
// Messages fp16 (attention weights fp32). CSR built on a side stream
// overlapped with GEMM1. Aggregations split across 2 warps (agg1) / 2
// half-warps (agg2) per node to halve the dependent-gather chains.
// ---------------------------------------------------------------------------

#define NMAX 50000
#define EMAX 800000

__device__ __align__(16) __half2 g_xlh [NMAX * 32];  // xl as half2 pairs
__device__ __align__(16) float g_as1[NMAX * 8];
__device__ __align__(16) float g_ad1[NMAX * 8];
__device__ __align__(16) __half2 g_hl2h[NMAX * 8];   // hl2 as half2 pairs
__device__ __align__(8)  float2 g_a2 [NMAX];         // (as2, ad2)

__device__ int g_cnt [NMAX];   // zero at module load; re-zeroed by k_scatter
__device__ int g_inc [NMAX];
__device__ int g_bsum[64];
__device__ int g_rptr[NMAX + 1];
__device__ int g_rank[EMAX];
__device__ int g_col [EMAX];

__device__ __forceinline__ float leaky02(float a) { return fmaxf(a, 0.2f * a); }

__device__ __forceinline__ float tf32r(float x) {
    uint32_t u;
    asm("cvt.rna.tf32.f32 %0, %1;" : "=r"(u) : "f"(x));
    return __uint_as_float(u);
}

__device__ __forceinline__ void mma_tf32(float4& c, uint32_t a0, uint32_t a1,
                                         uint32_t a2, uint32_t a3,
                                         uint32_t b0, uint32_t b1) {
    asm volatile(
        "mma.sync.aligned.m16n8k8.row.col.f32.tf32.tf32.f32 "
        "{%0,%1,%2,%3}, {%4,%5,%6,%7}, {%8,%9}, {%0,%1,%2,%3};\n"
        : "+f"(c.x), "+f"(c.y), "+f"(c.z), "+f"(c.w)
        : "r"(a0), "r"(a1), "r"(a2), "r"(a3), "r"(b0), "r"(b1));
}

// ----------------------------- CSR construction ----------------------------
__global__ void k_hist(const int* __restrict__ ei, int E) {
    int base = (blockIdx.x * blockDim.x + threadIdx.x) * 4;
    if (base >= E) return;
    int m = E - base; if (m > 4) m = 4;
    int d[4];
#pragma unroll
    for (int i = 0; i < 4; i++) if (i < m) d[i] = ei[E + base + i];
#pragma unroll
    for (int i = 0; i < 4; i++)
        if (i < m) g_rank[base + i] = atomicAdd(&g_cnt[d[i]], 1);
}

__global__ __launch_bounds__(1024) void k_scan1(int N) {
    __shared__ int sw[32];
    int t = threadIdx.x, i = blockIdx.x * 1024 + t;
    int lane = t & 31, wid = t >> 5;
    int s = (i < N) ? g_cnt[i] : 0;
#pragma unroll
    for (int o = 1; o < 32; o <<= 1) {
        int u = __shfl_up_sync(0xffffffffu, s, o);
        if (lane >= o) s += u;
    }
    if (lane == 31) sw[wid] = s;
    __syncthreads();
    if (wid == 0) {
        int ws = sw[lane];
#pragma unroll
        for (int o = 1; o < 32; o <<= 1) {
            int u = __shfl_up_sync(0xffffffffu, ws, o);
            if (lane >= o) ws += u;
        }
        sw[lane] = ws;
    }
    __syncthreads();
    int incl = s + (wid ? sw[wid - 1] : 0);
    if (i < N) g_inc[i] = incl;
    if (t == 1023) g_bsum[blockIdx.x] = incl;
}

__global__ void k_scan3(int N, int E, int ntiles) {
    __shared__ int sh[64];
    int t = threadIdx.x;
    if (t < 32) {
        int a = (t < ntiles) ? g_bsum[t] : 0;
        int b = (t + 32 < ntiles) ? g_bsum[t + 32] : 0;
#pragma unroll
        for (int o = 1; o < 32; o <<= 1) {
            int u = __shfl_up_sync(0xffffffffu, a, o);
            if (t >= o) a += u;
        }
        int tot = __shfl_sync(0xffffffffu, a, 31);
#pragma unroll
        for (int o = 1; o < 32; o <<= 1) {
            int u = __shfl_up_sync(0xffffffffu, b, o);
            if (t >= o) b += u;
        }
        sh[t] = a;
        sh[t + 32] = b + tot;
    }
    __syncthreads();
    int i = blockIdx.x * blockDim.x + t;
    if (i < N) {
        int blk = i >> 10;
        int excl = blk ? sh[blk - 1] : 0;
        g_rptr[i] = g_inc[i] - g_cnt[i] + excl;
    }
    if (i == 0) g_rptr[N] = E;
}

__global__ void k_scatter(const int* __restrict__ ei, int E, int N) {
    int tid = blockIdx.x * blockDim.x + threadIdx.x;
    if (tid < N) g_cnt[tid] = 0;
    int base = tid * 4;
    if (base >= E) return;
    int m = E - base; if (m > 4) m = 4;
    int d[4], s[4], r[4], rp[4];
#pragma unroll
    for (int i = 0; i < 4; i++)
        if (i < m) { d[i] = ei[E + base + i]; s[i] = ei[base + i]; }
#pragma unroll
    for (int i = 0; i < 4; i++) if (i < m) r[i] = g_rank[base + i];
#pragma unroll
    for (int i = 0; i < 4; i++) if (i < m) rp[i] = g_rptr[d[i]];
#pragma unroll
    for (int i = 0; i < 4; i++) if (i < m) g_col[rp[i] + r[i]] = s[i];
}

// --------------- GEMM1 (3xTF32 MMA) + fused node1 logits -------------------
#define G1_SMEM_BYTES (2 * 128 * 36 * 4 + 2 * 32 * 72 * 4)  // 55296

__global__ __launch_bounds__(256) void k_gemm1(const float* __restrict__ X,
                                               const float* __restrict__ W,
                                               const float* __restrict__ att_s,
                                               const float* __restrict__ att_d,
                                               int N) {
    extern __shared__ float smem[];
    float (*sAh)[36] = (float(*)[36])(smem);
    float (*sAl)[36] = (float(*)[36])(smem + 128 * 36);
    float (*sBh)[72] = (float(*)[72])(smem + 2 * 128 * 36);
    float (*sBl)[72] = (float(*)[72])(smem + 2 * 128 * 36 + 32 * 72);

    const int tid  = threadIdx.x;
    const int bm   = blockIdx.x * 128;
    const int warp = tid >> 5, lane = tid & 31;
    const int wm   = warp >> 1, wn = warp & 1;
    const int g    = lane >> 2, tig = lane & 3;

    const int ar = tid >> 1, ah = (tid & 1) * 16;
    const int bk = tid >> 3, bq = (tid & 7) * 8;

    int axr = bm + ar;
    if (axr >= N) axr = N - 1;
    const float4* Xr = (const float4*)(X + (size_t)axr * 512);

    float4 acc[2][4];
#pragma unroll
    for (int i = 0; i < 2; i++)
#pragma unroll
        for (int j = 0; j < 4; j++) acc[i][j] = make_float4(0.f, 0.f, 0.f, 0.f);

    float4 ra[4], rb[2];
#pragma unroll
    for (int i = 0; i < 4; i++) ra[i] = Xr[(ah >> 2) + i];
#pragma unroll
    for (int i = 0; i < 2; i++)
        rb[i] = ((const float4*)(W + (size_t)bk * 64 + bq))[i];

    for (int ks = 0; ks < 16; ks++) {
#pragma unroll
        for (int i = 0; i < 4; i++) {
            float4 h4 = make_float4(tf32r(ra[i].x), tf32r(ra[i].y),
                                    tf32r(ra[i].z), tf32r(ra[i].w));
            float4 l4 = make_float4(tf32r(ra[i].x - h4.x), tf32r(ra[i].y - h4.y),
                                    tf32r(ra[i].z - h4.z), tf32r(ra[i].w - h4.w));
            *(float4*)&sAh[ar][ah + i * 4] = h4;
            *(float4*)&sAl[ar][ah + i * 4] = l4;
        }
#pragma unroll
        for (int i = 0; i < 2; i++) {
            float4 h4 = make_float4(tf32r(rb[i].x), tf32r(rb[i].y),
                                    tf32r(rb[i].z), tf32r(rb[i].w));
            float4 l4 = make_float4(tf32r(rb[i].x - h4.x), tf32r(rb[i].y - h4.y),
                                    tf32r(rb[i].z - h4.z), tf32r(rb[i].w - h4.w));
            *(float4*)&sBh[bk][bq + i * 4] = h4;
            *(float4*)&sBl[bk][bq + i * 4] = l4;
        }
        __syncthreads();
        if (ks < 15) {
            int k0 = (ks + 1) * 32;
#pragma unroll
            for (int i = 0; i < 4; i++) ra[i] = Xr[((k0 + ah) >> 2) + i];
#pragma unroll
            for (int i = 0; i < 2; i++)
                rb[i] = ((const float4*)(W + (size_t)(k0 + bk) * 64 + bq))[i];
        }
#pragma unroll
        for (int ksub = 0; ksub < 4; ksub++) {
            const int kc = ksub * 8;
            uint32_t Ah[2][4], Al[2][4];
#pragma unroll
            for (int mt = 0; mt < 2; mt++) {
                const int r0 = wm * 32 + mt * 16 + g, r1 = r0 + 8;
                Ah[mt][0] = __float_as_uint(sAh[r0][kc + tig]);
                Ah[mt][1] = __float_as_uint(sAh[r1][kc + tig]);
                Ah[mt][2] = __float_as_uint(sAh[r0][kc + tig + 4]);
                Ah[mt][3] = __float_as_uint(sAh[r1][kc + tig + 4]);
                Al[mt][0] = __float_as_uint(sAl[r0][kc + tig]);
                Al[mt][1] = __float_as_uint(sAl[r1][kc + tig]);
                Al[mt][2] = __float_as_uint(sAl[r0][kc + tig + 4]);
                Al[mt][3] = __float_as_uint(sAl[r1][kc + tig + 4]);
            }
#pragma unroll
            for (int nt = 0; nt < 4; nt++) {
                const int nc = wn * 32 + nt * 8 + g;
                uint32_t bh0 = __float_as_uint(sBh[kc + tig][nc]);
                uint32_t bh1 = __float_as_uint(sBh[kc + tig + 4][nc]);
                uint32_t bl0 = __float_as_uint(sBl[kc + tig][nc]);
                uint32_t bl1 = __float_as_uint(sBl[kc + tig + 4][nc]);
#pragma unroll
                for (int mt = 0; mt < 2; mt++) {
                    mma_tf32(acc[mt][nt], Al[mt][0], Al[mt][1], Al[mt][2],
                             Al[mt][3], bh0, bh1);
                    mma_tf32(acc[mt][nt], Ah[mt][0], Ah[mt][1], Ah[mt][2],
                             Ah[mt][3], bl0, bl1);
                    mma_tf32(acc[mt][nt], Ah[mt][0], Ah[mt][1], Ah[mt][2],
                             Ah[mt][3], bh0, bh1);
                }
            }
        }
        __syncthreads();
    }

#pragma unroll
    for (int mt = 0; mt < 2; mt++) {
        const int row0 = bm + wm * 32 + mt * 16 + g;
        const int row1 = row0 + 8;
        float s0a[4], s1a[4], d0a[4], d1a[4];
#pragma unroll
        for (int nt = 0; nt < 4; nt++) {
            const int h = wn * 4 + nt;
            const int colh = h * 4 + tig;
            float4 a = acc[mt][nt];
            if (row0 < N)
                g_xlh[(size_t)row0 * 32 + colh] = __floats2half2_rn(a.x, a.y);
            if (row1 < N)
                g_xlh[(size_t)row1 * 32 + colh] = __floats2half2_rn(a.z, a.w);

            float2 asv = make_float2(__ldg(att_s + h * 8 + 2 * tig),
                                     __ldg(att_s + h * 8 + 2 * tig + 1));
            float2 adv = make_float2(__ldg(att_d + h * 8 + 2 * tig),
                                     __ldg(att_d + h * 8 + 2 * tig + 1));
            float s0 = a.x * asv.x + a.y * asv.y;
            float s1 = a.z * asv.x + a.w * asv.y;
            float d0 = a.x * adv.x + a.y * adv.y;
            float d1 = a.z * adv.x + a.w * adv.y;
#pragma unroll
            for (int off = 1; off < 4; off <<= 1) {
                s0 += __shfl_xor_sync(0xffffffffu, s0, off);
                s1 += __shfl_xor_sync(0xffffffffu, s1, off);
                d0 += __shfl_xor_sync(0xffffffffu, d0, off);
                d1 += __shfl_xor_sync(0xffffffffu, d1, off);
            }
            s0a[nt] = s0; s1a[nt] = s1; d0a[nt] = d0; d1a[nt] = d1;
        }
        if (tig == 0) {
            if (row0 < N) {
                *(float4*)&g_as1[row0 * 8 + wn * 4] =
                    make_float4(s0a[0], s0a[1], s0a[2], s0a[3]);
                *(float4*)&g_ad1[row0 * 8 + wn * 4] =
                    make_float4(d0a[0], d0a[1], d0a[2], d0a[3]);
            }
            if (row1 < N) {
                *(float4*)&g_as1[row1 * 8 + wn * 4] =
                    make_float4(s1a[0], s1a[1], s1a[2], s1a[3]);
                *(float4*)&g_ad1[row1 * 8 + wn * 4] =
                    make_float4(d1a[0], d1a[1], d1a[2], d1a[3]);
            }
        }
    }
}

// ---- layer1 aggregation (2 warps/node) + bias + layer2 GEMM + logits ------
// Block = 256 thr = 8 warps = 4 nodes. Warp pair (sub=0,1) splits edge range;
// partials merged in smem; sub0 warp runs the layer-2 epilogue.
__global__ __launch_bounds__(256) void k_agg1(const float* __restrict__ b1,
                                              const float* __restrict__ W2,
                                              const float* __restrict__ atts2,
                                              const float* __restrict__ attd2,
                                              int N) {
    __shared__ float pnum[8][64];
    __shared__ float pden[8][8];
    __shared__ float sh[4][64];
    const int tid = threadIdx.x;
    const int warp = tid >> 5, lane = tid & 31;
    const int nodeLocal = warp >> 1, sub = warp & 1;
    const int node = blockIdx.x * 4 + nodeLocal;
    const bool valid = node < N;
    const int d = valid ? node : N - 1;
    const int h = lane >> 2;
    const float ad = g_ad1[d * 8 + h];

    float nx = 0.f, ny = 0.f, den = 0.f;
    if (sub == 0) {  // self loop
        float w = __expf(leaky02(g_as1[d * 8 + h] + ad));
        float2 v = __half22float2(g_xlh[(size_t)d * 32 + lane]);
        nx = w * v.x; ny = w * v.y;
        den = ((lane & 3) == 0) ? w : 0.f;
    }
    const int r0 = g_rptr[d], r1 = g_rptr[d + 1];
    const int mid = (r0 + r1 + 1) >> 1;
    const int e0 = sub ? mid : r0;
    const int e1 = sub ? r1 : mid;
#pragma unroll 4
    for (int e = e0; e < e1; e++) {
        int s = g_col[e];
        float we = __expf(leaky02(g_as1[s * 8 + h] + ad));
        float2 xs = __half22float2(g_xlh[(size_t)s * 32 + lane]);
        nx += we * xs.x;
        ny += we * xs.y;
        if ((lane & 3) == 0) den += we;
    }
    if (sub) {
        pnum[warp][lane * 2]     = nx;
        pnum[warp][lane * 2 + 1] = ny;
        if ((lane & 3) == 0) pden[warp][h] = den;
    }
    __syncthreads();
    if (sub == 0 && valid) {
        nx += pnum[warp + 1][lane * 2];
        ny += pnum[warp + 1][lane * 2 + 1];
        if ((lane & 3) == 0) den += pden[warp + 1][h];
        float dfull = __shfl_sync(0xffffffffu, den, lane & ~3) + 1e-16f;
        float inv = 1.f / dfull;

        sh[nodeLocal][lane * 2]     = nx * inv + __ldg(b1 + lane * 2);
        sh[nodeLocal][lane * 2 + 1] = ny * inv + __ldg(b1 + lane * 2 + 1);
        __syncwarp();

        const int c = lane & 15;
        const int jb = (lane >> 4) * 32;
        float y = 0.f;
#pragma unroll
        for (int j2 = 0; j2 < 32; j2++) {
            int j = jb + j2;
            y += sh[nodeLocal][j] * __ldg(W2 + j * 16 + c);
        }
        y += __shfl_xor_sync(0xffffffffu, y, 16);

        float ynext = __shfl_down_sync(0xffffffffu, y, 1);
        if (lane < 16 && (c & 1) == 0)
            g_hl2h[(size_t)d * 8 + (c >> 1)] = __floats2half2_rn(y, ynext);

        float pa = y * __ldg(atts2 + c);
        float pd = y * __ldg(attd2 + c);
#pragma unroll
        for (int off = 8; off >= 1; off >>= 1) {
            pa += __shfl_xor_sync(0xffffffffu, pa, off);
            pd += __shfl_xor_sync(0xffffffffu, pd, off);
        }
        if (lane == 0) g_a2[d] = make_float2(pa, pd);
    }
}

// --- layer2 aggregation (full warp/node, 2 half-warp groups) + epilogue ----
__global__ __launch_bounds__(256) void k_agg2(const float* __restrict__ b2,
                                              float* __restrict__ out, int N) {
    int warp = (blockIdx.x * blockDim.x + threadIdx.x) >> 5;
    int lane = threadIdx.x & 31;
    int c = lane & 15;
    int grp = lane >> 4;
    bool valid = warp < N;
    const int d = valid ? warp : N - 1;
    const float2 a2d = g_a2[d];
    const float ad = a2d.y;

    float num = 0.f, den = 0.f;
    if (grp == 0) {  // self loop
        float w = __expf(leaky02(a2d.x + ad));
        float2 hv = __half22float2(g_hl2h[(size_t)d * 8 + (c >> 1)]);
        num = w * ((c & 1) ? hv.y : hv.x);
        den = w;
    }
    const int r0 = g_rptr[d], r1 = g_rptr[d + 1];
    const int mid = (r0 + r1 + 1) >> 1;
    const int e0 = grp ? mid : r0;
    const int e1 = grp ? r1 : mid;
#pragma unroll 4
    for (int e = e0; e < e1; e++) {
        int s = g_col[e];
        float2 a2s = g_a2[s];
        float we = __expf(leaky02(a2s.x + ad));
        float2 hs = __half22float2(g_hl2h[(size_t)s * 8 + (c >> 1)]);
        num += we * ((c & 1) ? hs.y : hs.x);
        den += we;
    }
    num += __shfl_xor_sync(0xffffffffu, num, 16);
    den += __shfl_xor_sync(0xffffffffu, den, 16);

    float x = num / (den + 1e-16f) + __ldg(b2 + c);
    x = (x > 0.f) ? x : (__expf(x) - 1.f);

    float m = x;
#pragma unroll
    for (int off = 1; off < 16; off <<= 1)
        m = fmaxf(m, __shfl_xor_sync(0xffffffffu, m, off));
    float ssum = __expf(x - m);
#pragma unroll
    for (int off = 1; off < 16; off <<= 1)
        ssum += __shfl_xor_sync(0xffffffffu, ssum, off);
    if (valid && grp == 0) out[(size_t)d * 16 + c] = x - m - __logf(ssum);
}

// ---------------------------------------------------------------------------
extern "C" void kernel_launch(void* const* d_in, const int* in_sizes, int n_in,
                              void* d_out, int out_size) {
    const float* x     = (const float*)d_in[0];
    const int*   ei    = (const int*)d_in[1];
    const float* W1    = (const float*)d_in[2];
    const float* atts1 = (const float*)d_in[3];
    const float* attd1 = (const float*)d_in[4];
    const float* b1    = (const float*)d_in[5];
    const float* W2    = (const float*)d_in[6];
    const float* atts2 = (const float*)d_in[7];
    const float* attd2 = (const float*)d_in[8];
    const float* b2    = (const float*)d_in[9];
    float* out = (float*)d_out;

    const int N = in_sizes[0] / 512;
    const int E = in_sizes[1] / 2;
    const int ntiles = (N + 1023) >> 10;

    static cudaStream_t s_csr = nullptr;
    static cudaEvent_t ev_fork = nullptr, ev_join = nullptr;
    if (!s_csr) {
        cudaFuncSetAttribute(k_gemm1, cudaFuncAttributeMaxDynamicSharedMemorySize,
                             G1_SMEM_BYTES);
        cudaStreamCreateWithFlags(&s_csr, cudaStreamNonBlocking);
        cudaEventCreateWithFlags(&ev_fork, cudaEventDisableTiming);
        cudaEventCreateWithFlags(&ev_join, cudaEventDisableTiming);
    }

    // fork: CSR build on s_csr, GEMM1 on the main stream
    cudaEventRecord(ev_fork, 0);
    cudaStreamWaitEvent(s_csr, ev_fork, 0);

    k_hist<<<(E / 4 + 255) / 256, 256, 0, s_csr>>>(ei, E);
    k_scan1<<<ntiles, 1024, 0, s_csr>>>(N);
    k_scan3<<<(N + 255) / 256, 256, 0, s_csr>>>(N, E, ntiles);
    k_scatter<<<(E / 4 + 255) / 256, 256, 0, s_csr>>>(ei, E, N);
    cudaEventRecord(ev_join, s_csr);

    k_gemm1<<<(N + 127) / 128, 256, G1_SMEM_BYTES>>>(x, W1, atts1, attd1, N);

    // join: aggregation needs both CSR and GEMM1
    cudaStreamWaitEvent(0, ev_join, 0);

    k_agg1<<<(N + 3) / 4, 256>>>(b1, W2, atts2, attd2, N);
    k_agg2<<<(N * 32 + 255) / 256, 256>>>(b2, out, N);
}

// round 12
// speedup vs baseline: 1.3801x; 1.3801x over previous
#include <cuda_runtime.h>
#include <cuda_fp16.h>
#include <cstdint>

// ---------------------------------------------------------------------------
// GATNet 2-layer GAT, N=50000, E=800000 (+self loops).
// GEMM1 = 3xFP16 tensor-core GEMM (Markidis split: hh+hl+lh, f32 accum;
// error bound identical to 3xTF32, 2x tensor throughput) with fused logits.
// Messages fp16; CSR built on side stream overlapped with GEMM1.
// agg1 fuses layer-1 aggregation + bias + layer-2 GEMM + layer-2 logits.
// ---------------------------------------------------------------------------

#define NMAX 50000
#define EMAX 800000

__device__ __align__(16) __half2 g_xlh [NMAX * 32];  // xl as half2 pairs
__device__ __align__(16) float g_as1[NMAX * 8];
__device__ __align__(16) float g_ad1[NMAX * 8];
__device__ __align__(16) float g_hl2[NMAX * 16];
__device__ float g_as2[NMAX];
__device__ float g_ad2[NMAX];

__device__ int g_cnt [NMAX];   // zero at module load; re-zeroed by k_scatter
__device__ int g_inc [NMAX];
__device__ int g_bsum[64];
__device__ int g_rptr[NMAX + 1];
__device__ int g_rank[EMAX];
__device__ int g_col [EMAX];

__device__ __forceinline__ float leaky02(float a) { return fmaxf(a, 0.2f * a); }

// split (x,y) into hi/lo half2 pairs (packed as u32)
__device__ __forceinline__ void split2(float x, float y,
                                       uint32_t& h, uint32_t& l) {
    __half hx = __float2half_rn(x), hy = __float2half_rn(y);
    __half lx = __float2half_rn(x - __half2float(hx));
    __half ly = __float2half_rn(y - __half2float(hy));
    __half2 hh = __halves2half2(hx, hy), ll = __halves2half2(lx, ly);
    h = *reinterpret_cast<uint32_t*>(&hh);
    l = *reinterpret_cast<uint32_t*>(&ll);
}

__device__ __forceinline__ void mma_f16(float4& c, uint32_t a0, uint32_t a1,
                                        uint32_t a2, uint32_t a3,
                                        uint32_t b0, uint32_t b1) {
    asm volatile(
        "mma.sync.aligned.m16n8k16.row.col.f32.f16.f16.f32 "
        "{%0,%1,%2,%3}, {%4,%5,%6,%7}, {%8,%9}, {%0,%1,%2,%3};\n"
        : "+f"(c.x), "+f"(c.y), "+f"(c.z), "+f"(c.w)
        : "r"(a0), "r"(a1), "r"(a2), "r"(a3), "r"(b0), "r"(b1));
}

// ----------------------------- CSR construction ----------------------------
__global__ void k_hist(const int* __restrict__ ei, int E) {
    int base = (blockIdx.x * blockDim.x + threadIdx.x) * 4;
    if (base >= E) return;
    int m = E - base; if (m > 4) m = 4;
    int d[4];
#pragma unroll
    for (int i = 0; i < 4; i++) if (i < m) d[i] = ei[E + base + i];
#pragma unroll
    for (int i = 0; i < 4; i++)
        if (i < m) g_rank[base + i] = atomicAdd(&g_cnt[d[i]], 1);
}

__global__ __launch_bounds__(1024) void k_scan1(int N) {
    __shared__ int sw[32];
    int t = threadIdx.x, i = blockIdx.x * 1024 + t;
    int lane = t & 31, wid = t >> 5;
    int s = (i < N) ? g_cnt[i] : 0;
#pragma unroll
    for (int o = 1; o < 32; o <<= 1) {
        int u = __shfl_up_sync(0xffffffffu, s, o);
        if (lane >= o) s += u;
    }
    if (lane == 31) sw[wid] = s;
    __syncthreads();
    if (wid == 0) {
        int ws = sw[lane];
#pragma unroll
        for (int o = 1; o < 32; o <<= 1) {
            int u = __shfl_up_sync(0xffffffffu, ws, o);
            if (lane >= o) ws += u;
        }
        sw[lane] = ws;
    }
    __syncthreads();
    int incl = s + (wid ? sw[wid - 1] : 0);
    if (i < N) g_inc[i] = incl;
    if (t == 1023) g_bsum[blockIdx.x] = incl;
}

__global__ void k_scan3(int N, int E, int ntiles) {
    __shared__ int sh[64];
    int t = threadIdx.x;
    if (t < 32) {
        int a = (t < ntiles) ? g_bsum[t] : 0;
        int b = (t + 32 < ntiles) ? g_bsum[t + 32] : 0;
#pragma unroll
        for (int o = 1; o < 32; o <<= 1) {
            int u = __shfl_up_sync(0xffffffffu, a, o);
            if (t >= o) a += u;
        }
        int tot = __shfl_sync(0xffffffffu, a, 31);
#pragma unroll
        for (int o = 1; o < 32; o <<= 1) {
            int u = __shfl_up_sync(0xffffffffu, b, o);
            if (t >= o) b += u;
        }
        sh[t] = a;
        sh[t + 32] = b + tot;
    }
    __syncthreads();
    int i = blockIdx.x * blockDim.x + t;
    if (i < N) {
        int blk = i >> 10;
        int excl = blk ? sh[blk - 1] : 0;
        g_rptr[i] = g_inc[i] - g_cnt[i] + excl;
    }
    if (i == 0) g_rptr[N] = E;
}

__global__ void k_scatter(const int* __restrict__ ei, int E, int N) {
    int tid = blockIdx.x * blockDim.x + threadIdx.x;
    if (tid < N) g_cnt[tid] = 0;
    int base = tid * 4;
    if (base >= E) return;
    int m = E - base; if (m > 4) m = 4;
    int d[4], s[4], r[4], rp[4];
#pragma unroll
    for (int i = 0; i < 4; i++)
        if (i < m) { d[i] = ei[E + base + i]; s[i] = ei[base + i]; }
#pragma unroll
    for (int i = 0; i < 4; i++) if (i < m) r[i] = g_rank[base + i];
#pragma unroll
    for (int i = 0; i < 4; i++) if (i < m) rp[i] = g_rptr[d[i]];
#pragma unroll
    for (int i = 0; i < 4; i++) if (i < m) g_col[rp[i] + r[i]] = s[i];
}

// --------------- GEMM1 (3xFP16 MMA m16n8k16) + fused node1 logits ----------
// xl = X @ W1, block tile 128x64, BK=32, 8 warps = 4(M) x 2(N), warp 32x32.
__global__ __launch_bounds__(256) void k_gemm1(const float* __restrict__ X,
                                               const float* __restrict__ W,
                                               const float* __restrict__ att_s,
                                               const float* __restrict__ att_d,
                                               int N) {
    // half2 tiles, k-paired; pads chosen conflict-free (20 / 72 half2)
    __shared__ __align__(16) __half2 sAh2[128][20];
    __shared__ __align__(16) __half2 sAl2[128][20];
    __shared__ __align__(16) __half2 sBh2[16][72];
    __shared__ __align__(16) __half2 sBl2[16][72];

    const int tid  = threadIdx.x;
    const int bm   = blockIdx.x * 128;
    const int warp = tid >> 5, lane = tid & 31;
    const int wm   = warp >> 1, wn = warp & 1;
    const int g    = lane >> 2, tig = lane & 3;

    // loaders: A 128x32 floats (16/thr), B 32x64 floats (2 k-rows x 4 cols/thr)
    const int ar  = tid >> 1, af4 = (tid & 1) * 4, ah2 = (tid & 1) * 8;
    const int bkk = tid >> 4, bq = (tid & 15) * 4;

    int axr = bm + ar;
    if (axr >= N) axr = N - 1;   // clamp; stores guarded
    const float4* Xr = (const float4*)(X + (size_t)axr * 512);

    float4 acc[2][4];
#pragma unroll
    for (int i = 0; i < 2; i++)
#pragma unroll
        for (int j = 0; j < 4; j++) acc[i][j] = make_float4(0.f, 0.f, 0.f, 0.f);

    float4 ra[4], rb0, rb1;
#pragma unroll
    for (int i = 0; i < 4; i++) ra[i] = Xr[af4 + i];
    rb0 = *(const float4*)(W + (size_t)(2 * bkk) * 64 + bq);
    rb1 = *(const float4*)(W + (size_t)(2 * bkk + 1) * 64 + bq);

    for (int ks = 0; ks < 16; ks++) {
        // split + store A (8 half2 hi + 8 lo per thread, 2 uint4 stores each)
        uint32_t AH[8], AL[8];
#pragma unroll
        for (int i = 0; i < 4; i++) {
            split2(ra[i].x, ra[i].y, AH[2 * i],     AL[2 * i]);
            split2(ra[i].z, ra[i].w, AH[2 * i + 1], AL[2 * i + 1]);
        }
        *(uint4*)&sAh2[ar][ah2]     = *(uint4*)&AH[0];
        *(uint4*)&sAh2[ar][ah2 + 4] = *(uint4*)&AH[4];
        *(uint4*)&sAl2[ar][ah2]     = *(uint4*)&AL[0];
        *(uint4*)&sAl2[ar][ah2 + 4] = *(uint4*)&AL[4];
        // split + store B (pairs across two k-rows)
        uint32_t BH[4], BL[4];
        split2(rb0.x, rb1.x, BH[0], BL[0]);
        split2(rb0.y, rb1.y, BH[1], BL[1]);
        split2(rb0.z, rb1.z, BH[2], BL[2]);
        split2(rb0.w, rb1.w, BH[3], BL[3]);
        *(uint4*)&sBh2[bkk][bq] = *(uint4*)&BH[0];
        *(uint4*)&sBl2[bkk][bq] = *(uint4*)&BL[0];
        __syncthreads();

        if (ks < 15) {
            int k0 = (ks + 1) * 32;
#pragma unroll
            for (int i = 0; i < 4; i++) ra[i] = Xr[(k0 >> 2) + af4 + i];
            rb0 = *(const float4*)(W + (size_t)(k0 + 2 * bkk) * 64 + bq);
            rb1 = *(const float4*)(W + (size_t)(k0 + 2 * bkk + 1) * 64 + bq);
        }

#pragma unroll
        for (int ki = 0; ki < 2; ki++) {
            const int kc2 = ki * 8;
            uint32_t Ah[2][4], Al[2][4];
#pragma unroll
            for (int mt = 0; mt < 2; mt++) {
                const int r0 = wm * 32 + mt * 16 + g, r8 = r0 + 8;
                Ah[mt][0] = *(const uint32_t*)&sAh2[r0][kc2 + tig];
                Ah[mt][1] = *(const uint32_t*)&sAh2[r8][kc2 + tig];
                Ah[mt][2] = *(const uint32_t*)&sAh2[r0][kc2 + tig + 4];
                Ah[mt][3] = *(const uint32_t*)&sAh2[r8][kc2 + tig + 4];
                Al[mt][0] = *(const uint32_t*)&sAl2[r0][kc2 + tig];
                Al[mt][1] = *(const uint32_t*)&sAl2[r8][kc2 + tig];
                Al[mt][2] = *(const uint32_t*)&sAl2[r0][kc2 + tig + 4];
                Al[mt][3] = *(const uint32_t*)&sAl2[r8][kc2 + tig + 4];
            }
#pragma unroll
            for (int nt = 0; nt < 4; nt++) {
                const int nc = wn * 32 + nt * 8 + g;
                uint32_t bh0 = *(const uint32_t*)&sBh2[kc2 + tig][nc];
                uint32_t bh1 = *(const uint32_t*)&sBh2[kc2 + tig + 4][nc];
                uint32_t bl0 = *(const uint32_t*)&sBl2[kc2 + tig][nc];
                uint32_t bl1 = *(const uint32_t*)&sBl2[kc2 + tig + 4][nc];
#pragma unroll
                for (int mt = 0; mt < 2; mt++) {
                    mma_f16(acc[mt][nt], Al[mt][0], Al[mt][1], Al[mt][2],
                            Al[mt][3], bh0, bh1);
                    mma_f16(acc[mt][nt], Ah[mt][0], Ah[mt][1], Ah[mt][2],
                            Ah[mt][3], bl0, bl1);
                    mma_f16(acc[mt][nt], Ah[mt][0], Ah[mt][1], Ah[mt][2],
                            Ah[mt][3], bh0, bh1);
                }
            }
        }
        __syncthreads();
    }

#pragma unroll
    for (int mt = 0; mt < 2; mt++) {
        const int row0 = bm + wm * 32 + mt * 16 + g;
        const int row1 = row0 + 8;
        float s0a[4], s1a[4], d0a[4], d1a[4];
#pragma unroll
        for (int nt = 0; nt < 4; nt++) {
            const int h = wn * 4 + nt;
            const int colh = h * 4 + tig;
            float4 a = acc[mt][nt];
            if (row0 < N)
                g_xlh[(size_t)row0 * 32 + colh] = __floats2half2_rn(a.x, a.y);
            if (row1 < N)
                g_xlh[(size_t)row1 * 32 + colh] = __floats2half2_rn(a.z, a.w);

            float2 asv = make_float2(__ldg(att_s + h * 8 + 2 * tig),
                                     __ldg(att_s + h * 8 + 2 * tig + 1));
            float2 adv = make_float2(__ldg(att_d + h * 8 + 2 * tig),
                                     __ldg(att_d + h * 8 + 2 * tig + 1));
            float s0 = a.x * asv.x + a.y * asv.y;
            float s1 = a.z * asv.x + a.w * asv.y;
            float d0 = a.x * adv.x + a.y * adv.y;
            float d1 = a.z * adv.x + a.w * adv.y;
#pragma unroll
            for (int off = 1; off < 4; off <<= 1) {
                s0 += __shfl_xor_sync(0xffffffffu, s0, off);
                s1 += __shfl_xor_sync(0xffffffffu, s1, off);
                d0 += __shfl_xor_sync(0xffffffffu, d0, off);
                d1 += __shfl_xor_sync(0xffffffffu, d1, off);
            }
            s0a[nt] = s0; s1a[nt] = s1; d0a[nt] = d0; d1a[nt] = d1;
        }
        if (tig == 0) {
            if (row0 < N) {
                *(float4*)&g_as1[row0 * 8 + wn * 4] =
                    make_float4(s0a[0], s0a[1], s0a[2], s0a[3]);
                *(float4*)&g_ad1[row0 * 8 + wn * 4] =
                    make_float4(d0a[0], d0a[1], d0a[2], d0a[3]);
            }
            if (row1 < N) {
                *(float4*)&g_as1[row1 * 8 + wn * 4] =
                    make_float4(s1a[0], s1a[1], s1a[2], s1a[3]);
                *(float4*)&g_ad1[row1 * 8 + wn * 4] =
                    make_float4(d1a[0], d1a[1], d1a[2], d1a[3]);
            }
        }
    }
}

// ---- layer1 aggregation + bias + layer2 GEMM + layer2 logits (fused) ------
__global__ __launch_bounds__(256) void k_agg1(const float* __restrict__ b1,
                                              const float* __restrict__ W2,
                                              const float* __restrict__ atts2,
                                              const float* __restrict__ attd2,
                                              int N) {
    __shared__ float sh[8][64];
    int warp = (blockIdx.x * blockDim.x + threadIdx.x) >> 5;
    int wl = (threadIdx.x >> 5);
    int lane = threadIdx.x & 31;
    if (warp >= N) return;
    const int d = warp;
    const int h = lane >> 2;
    const float ad = g_ad1[d * 8 + h];

    float w = __expf(leaky02(g_as1[d * 8 + h] + ad));
    float2 v = __half22float2(g_xlh[(size_t)d * 32 + lane]);
    float nx = w * v.x, ny = w * v.y;
    float den = ((lane & 3) == 0) ? w : 0.f;

    const int e1 = g_rptr[d + 1];
#pragma unroll 4
    for (int e = g_rptr[d]; e < e1; e++) {
        int s = g_col[e];
        float we = __expf(leaky02(g_as1[s * 8 + h] + ad));
        float2 xs = __half22float2(g_xlh[(size_t)s * 32 + lane]);
        nx += we * xs.x;
        ny += we * xs.y;
        if ((lane & 3) == 0) den += we;
    }
    float dfull = __shfl_sync(0xffffffffu, den, lane & ~3) + 1e-16f;
    float inv = 1.f / dfull;

    sh[wl][lane * 2]     = nx * inv + __ldg(b1 + lane * 2);
    sh[wl][lane * 2 + 1] = ny * inv + __ldg(b1 + lane * 2 + 1);
    __syncwarp();

    const int c = lane & 15;
    const int jb = (lane >> 4) * 32;
    float y = 0.f;
#pragma unroll
    for (int j2 = 0; j2 < 32; j2++) {
        int j = jb + j2;
        y += sh[wl][j] * __ldg(W2 + j * 16 + c);
    }
    y += __shfl_xor_sync(0xffffffffu, y, 16);

    if (lane < 16) g_hl2[(size_t)d * 16 + c] = y;

    float pa = y * __ldg(atts2 + c);
    float pd = y * __ldg(attd2 + c);
#pragma unroll
    for (int off = 8; off >= 1; off >>= 1) {
        pa += __shfl_xor_sync(0xffffffffu, pa, off);
        pd += __shfl_xor_sync(0xffffffffu, pd, off);
    }
    if (lane == 0) {
        g_as2[d] = pa;
        g_ad2[d] = pd;
    }
}

// ------ layer2 aggregation + bias + elu + log_softmax (16 lanes/node) ------
__global__ __launch_bounds__(256) void k_agg2(const float* __restrict__ b2,
                                              float* __restrict__ out, int N) {
    int gid = (blockIdx.x * blockDim.x + threadIdx.x) >> 4;
    int c = threadIdx.x & 15;
    bool valid = gid < N;
    const int d = valid ? gid : 0;
    const float ad = g_ad2[d];

    float w = __expf(leaky02(g_as2[d] + ad));
    float num = w * g_hl2[(size_t)d * 16 + c];
    float den = w;

    const int e1 = g_rptr[d + 1];
#pragma unroll 4
    for (int e = g_rptr[d]; e < e1; e++) {
        int s = g_col[e];
        float we = __expf(leaky02(g_as2[s] + ad));
        num += we * g_hl2[(size_t)s * 16 + c];
        den += we;
    }
    float x = num / (den + 1e-16f) + __ldg(b2 + c);
    x = (x > 0.f) ? x : (__expf(x) - 1.f);

    float m = x;
#pragma unroll
    for (int off = 1; off < 16; off <<= 1)
        m = fmaxf(m, __shfl_xor_sync(0xffffffffu, m, off));
    float ssum = __expf(x - m);
#pragma unroll
    for (int off = 1; off < 16; off <<= 1)
        ssum += __shfl_xor_sync(0xffffffffu, ssum, off);
    if (valid) out[(size_t)d * 16 + c] = x - m - __logf(ssum);
}

// ---------------------------------------------------------------------------
extern "C" void kernel_launch(void* const* d_in, const int* in_sizes, int n_in,
                              void* d_out, int out_size) {
    const float* x     = (const float*)d_in[0];
    const int*   ei    = (const int*)d_in[1];
    const float* W1    = (const float*)d_in[2];
    const float* atts1 = (const float*)d_in[3];
    const float* attd1 = (const float*)d_in[4];
    const float* b1    = (const float*)d_in[5];
    const float* W2    = (const float*)d_in[6];
    const float* atts2 = (const float*)d_in[7];
    const float* attd2 = (const float*)d_in[8];
    const float* b2    = (const float*)d_in[9];
    float* out = (float*)d_out;

    const int N = in_sizes[0] / 512;
    const int E = in_sizes[1] / 2;
    const int ntiles = (N + 1023) >> 10;

    static cudaStream_t s_csr = nullptr;
    static cudaEvent_t ev_fork = nullptr, ev_join = nullptr;
    if (!s_csr) {
        cudaStreamCreateWithFlags(&s_csr, cudaStreamNonBlocking);
        cudaEventCreateWithFlags(&ev_fork, cudaEventDisableTiming);
        cudaEventCreateWithFlags(&ev_join, cudaEventDisableTiming);
    }

    // fork: CSR build on s_csr, GEMM1 on the main stream
    cudaEventRecord(ev_fork, 0);
    cudaStreamWaitEvent(s_csr, ev_fork, 0);

    k_hist<<<(E / 4 + 255) / 256, 256, 0, s_csr>>>(ei, E);
    k_scan1<<<ntiles, 1024, 0, s_csr>>>(N);
    k_scan3<<<(N + 255) / 256, 256, 0, s_csr>>>(N, E, ntiles);
    k_scatter<<<(E / 4 + 255) / 256, 256, 0, s_csr>>>(ei, E, N);
    cudaEventRecord(ev_join, s_csr);

    k_gemm1<<<(N + 127) / 128, 256>>>(x, W1, atts1, attd1, N);

    // join: aggregation needs both CSR and GEMM1
    cudaStreamWaitEvent(0, ev_join, 0);

    k_agg1<<<(N * 32 + 255) / 256, 256>>>(b1, W2, atts2, attd2, N);
    k_agg2<<<(N * 16 + 255) / 256, 256>>>(b2, out, N);
}

// round 13
// speedup vs baseline: 1.3888x; 1.0064x over previous
#include <cuda_runtime.h>
#include <cuda_fp16.h>
#include <cstdint>

// ---------------------------------------------------------------------------
// GATNet 2-layer GAT, N=50000, E=800000 (+self loops).
// GEMM1 = 3xFP16 tensor-core GEMM (Markidis split: hh+hl+lh, f32 accum;
// error bound identical to 3xTF32, 2x tensor throughput) with fused logits.
// Messages fp16; CSR built on side stream overlapped with GEMM1.
// agg1 fuses layer-1 aggregation + bias + layer-2 GEMM + layer-2 logits.
// ---------------------------------------------------------------------------

#define NMAX 50000
#define EMAX 800000

__device__ __align__(16) __half2 g_xlh [NMAX * 32];  // xl as half2 pairs
__device__ __align__(16) float g_as1[NMAX * 8];
__device__ __align__(16) float g_ad1[NMAX * 8];
__device__ __align__(16) float g_hl2[NMAX * 16];
__device__ float g_as2[NMAX];
__device__ float g_ad2[NMAX];

__device__ int g_cnt [NMAX];   // zero at module load; re-zeroed by k_scatter
__device__ int g_inc [NMAX];
__device__ int g_bsum[64];
__device__ int g_rptr[NMAX + 1];
__device__ int g_rank[EMAX];
__device__ int g_col [EMAX];

__device__ __forceinline__ float leaky02(float a) { return fmaxf(a, 0.2f * a); }

// split (x,y) into hi/lo half2 pairs (packed as u32)
__device__ __forceinline__ void split2(float x, float y,
                                       uint32_t& h, uint32_t& l) {
    __half hx = __float2half_rn(x), hy = __float2half_rn(y);
    __half lx = __float2half_rn(x - __half2float(hx));
    __half ly = __float2half_rn(y - __half2float(hy));
    __half2 hh = __halves2half2(hx, hy), ll = __halves2half2(lx, ly);
    h = *reinterpret_cast<uint32_t*>(&hh);
    l = *reinterpret_cast<uint32_t*>(&ll);
}

__device__ __forceinline__ void mma_f16(float4& c, uint32_t a0, uint32_t a1,
                                        uint32_t a2, uint32_t a3,
                                        uint32_t b0, uint32_t b1) {
    asm volatile(
        "mma.sync.aligned.m16n8k16.row.col.f32.f16.f16.f32 "
        "{%0,%1,%2,%3}, {%4,%5,%6,%7}, {%8,%9}, {%0,%1,%2,%3};\n"
        : "+f"(c.x), "+f"(c.y), "+f"(c.z), "+f"(c.w)
        : "r"(a0), "r"(a1), "r"(a2), "r"(a3), "r"(b0), "r"(b1));
}

// ----------------------------- CSR construction ----------------------------
__global__ void k_hist(const int* __restrict__ ei, int E) {
    int base = (blockIdx.x * blockDim.x + threadIdx.x) * 4;
    if (base >= E) return;
    int m = E - base; if (m > 4) m = 4;
    int d[4];
#pragma unroll
    for (int i = 0; i < 4; i++) if (i < m) d[i] = ei[E + base + i];
#pragma unroll
    for (int i = 0; i < 4; i++)
        if (i < m) g_rank[base + i] = atomicAdd(&g_cnt[d[i]], 1);
}

__global__ __launch_bounds__(1024) void k_scan1(int N) {
    __shared__ int sw[32];
    int t = threadIdx.x, i = blockIdx.x * 1024 + t;
    int lane = t & 31, wid = t >> 5;
    int s = (i < N) ? g_cnt[i] : 0;
#pragma unroll
    for (int o = 1; o < 32; o <<= 1) {
        int u = __shfl_up_sync(0xffffffffu, s, o);
        if (lane >= o) s += u;
    }
    if (lane == 31) sw[wid] = s;
    __syncthreads();
    if (wid == 0) {
        int ws = sw[lane];
#pragma unroll
        for (int o = 1; o < 32; o <<= 1) {
            int u = __shfl_up_sync(0xffffffffu, ws, o);
            if (lane >= o) ws += u;
        }
        sw[lane] = ws;
    }
    __syncthreads();
    int incl = s + (wid ? sw[wid - 1] : 0);
    if (i < N) g_inc[i] = incl;
    if (t == 1023) g_bsum[blockIdx.x] = incl;
}

__global__ void k_scan3(int N, int E, int ntiles) {
    __shared__ int sh[64];
    int t = threadIdx.x;
    if (t < 32) {
        int a = (t < ntiles) ? g_bsum[t] : 0;
        int b = (t + 32 < ntiles) ? g_bsum[t + 32] : 0;
#pragma unroll
        for (int o = 1; o < 32; o <<= 1) {
            int u = __shfl_up_sync(0xffffffffu, a, o);
            if (t >= o) a += u;
        }
        int tot = __shfl_sync(0xffffffffu, a, 31);
#pragma unroll
        for (int o = 1; o < 32; o <<= 1) {
            int u = __shfl_up_sync(0xffffffffu, b, o);
            if (t >= o) b += u;
        }
        sh[t] = a;
        sh[t + 32] = b + tot;
    }
    __syncthreads();
    int i = blockIdx.x * blockDim.x + t;
    if (i < N) {
        int blk = i >> 10;
        int excl = blk ? sh[blk - 1] : 0;
        g_rptr[i] = g_inc[i] - g_cnt[i] + excl;
    }
    if (i == 0) g_rptr[N] = E;
}

__global__ void k_scatter(const int* __restrict__ ei, int E, int N) {
    int tid = blockIdx.x * blockDim.x + threadIdx.x;
    if (tid < N) g_cnt[tid] = 0;
    int base = tid * 4;
    if (base >= E) return;
    int m = E - base; if (m > 4) m = 4;
    int d[4], s[4], r[4], rp[4];
#pragma unroll
    for (int i = 0; i < 4; i++)
        if (i < m) { d[i] = ei[E + base + i]; s[i] = ei[base + i]; }
#pragma unroll
    for (int i = 0; i < 4; i++) if (i < m) r[i] = g_rank[base + i];
#pragma unroll
    for (int i = 0; i < 4; i++) if (i < m) rp[i] = g_rptr[d[i]];
#pragma unroll
    for (int i = 0; i < 4; i++) if (i < m) g_col[rp[i] + r[i]] = s[i];
}

// --------------- GEMM1 (3xFP16 MMA m16n8k16) + fused node1 logits ----------
// xl = X @ W1, block tile 128x64, BK=32, 8 warps = 4(M) x 2(N), warp 32x32.
__global__ __launch_bounds__(256) void k_gemm1(const float* __restrict__ X,
                                               const float* __restrict__ W,
                                               const float* __restrict__ att_s,
                                               const float* __restrict__ att_d,
                                               int N) {
    // half2 tiles, k-paired; pads chosen conflict-free (20 / 72 half2)
    __shared__ __align__(16) __half2 sAh2[128][20];
    __shared__ __align__(16) __half2 sAl2[128][20];
    __shared__ __align__(16) __half2 sBh2[16][72];
    __shared__ __align__(16) __half2 sBl2[16][72];

    const int tid  = threadIdx.x;
    const int bm   = blockIdx.x * 128;
    const int warp = tid >> 5, lane = tid & 31;
    const int wm   = warp >> 1, wn = warp & 1;
    const int g    = lane >> 2, tig = lane & 3;

    // loaders: A 128x32 floats (16/thr), B 32x64 floats (2 k-rows x 4 cols/thr)
    const int ar  = tid >> 1, af4 = (tid & 1) * 4, ah2 = (tid & 1) * 8;
    const int bkk = tid >> 4, bq = (tid & 15) * 4;

    int axr = bm + ar;
    if (axr >= N) axr = N - 1;   // clamp; stores guarded
    const float4* Xr = (const float4*)(X + (size_t)axr * 512);

    float4 acc[2][4];
#pragma unroll
    for (int i = 0; i < 2; i++)
#pragma unroll
        for (int j = 0; j < 4; j++) acc[i][j] = make_float4(0.f, 0.f, 0.f, 0.f);

    float4 ra[4], rb0, rb1;
#pragma unroll
    for (int i = 0; i < 4; i++) ra[i] = Xr[af4 + i];
    rb0 = *(const float4*)(W + (size_t)(2 * bkk) * 64 + bq);
    rb1 = *(const float4*)(W + (size_t)(2 * bkk + 1) * 64 + bq);

    for (int ks = 0; ks < 16; ks++) {
        // split + store A (8 half2 hi + 8 lo per thread, 2 uint4 stores each)
        uint32_t AH[8], AL[8];
#pragma unroll
        for (int i = 0; i < 4; i++) {
            split2(ra[i].x, ra[i].y, AH[2 * i],     AL[2 * i]);
            split2(ra[i].z, ra[i].w, AH[2 * i + 1], AL[2 * i + 1]);
        }
        *(uint4*)&sAh2[ar][ah2]     = *(uint4*)&AH[0];
        *(uint4*)&sAh2[ar][ah2 + 4] = *(uint4*)&AH[4];
        *(uint4*)&sAl2[ar][ah2]     = *(uint4*)&AL[0];
        *(uint4*)&sAl2[ar][ah2 + 4] = *(uint4*)&AL[4];
        // split + store B (pairs across two k-rows)
        uint32_t BH[4], BL[4];
        split2(rb0.x, rb1.x, BH[0], BL[0]);
        split2(rb0.y, rb1.y, BH[1], BL[1]);
        split2(rb0.z, rb1.z, BH[2], BL[2]);
        split2(rb0.w, rb1.w, BH[3], BL[3]);
        *(uint4*)&sBh2[bkk][bq] = *(uint4*)&BH[0];
        *(uint4*)&sBl2[bkk][bq] = *(uint4*)&BL[0];
        __syncthreads();

        if (ks < 15) {
            int k0 = (ks + 1) * 32;
#pragma unroll
            for (int i = 0; i < 4; i++) ra[i] = Xr[(k0 >> 2) + af4 + i];
            rb0 = *(const float4*)(W + (size_t)(k0 + 2 * bkk) * 64 + bq);
            rb1 = *(const float4*)(W + (size_t)(k0 + 2 * bkk + 1) * 64 + bq);
        }

#pragma unroll
        for (int ki = 0; ki < 2; ki++) {
            const int kc2 = ki * 8;
            uint32_t Ah[2][4], Al[2][4];
#pragma unroll
            for (int mt = 0; mt < 2; mt++) {
                const int r0 = wm * 32 + mt * 16 + g, r8 = r0 + 8;
                Ah[mt][0] = *(const uint32_t*)&sAh2[r0][kc2 + tig];
                Ah[mt][1] = *(const uint32_t*)&sAh2[r8][kc2 + tig];
                Ah[mt][2] = *(const uint32_t*)&sAh2[r0][kc2 + tig + 4];
                Ah[mt][3] = *(const uint32_t*)&sAh2[r8][kc2 + tig + 4];
                Al[mt][0] = *(const uint32_t*)&sAl2[r0][kc2 + tig];
                Al[mt][1] = *(const uint32_t*)&sAl2[r8][kc2 + tig];
                Al[mt][2] = *(const uint32_t*)&sAl2[r0][kc2 + tig + 4];
                Al[mt][3] = *(const uint32_t*)&sAl2[r8][kc2 + tig + 4];
            }
#pragma unroll
            for (int nt = 0; nt < 4; nt++) {
                const int nc = wn * 32 + nt * 8 + g;
                uint32_t bh0 = *(const uint32_t*)&sBh2[kc2 + tig][nc];
                uint32_t bh1 = *(const uint32_t*)&sBh2[kc2 + tig + 4][nc];
                uint32_t bl0 = *(const uint32_t*)&sBl2[kc2 + tig][nc];
                uint32_t bl1 = *(const uint32_t*)&sBl2[kc2 + tig + 4][nc];
#pragma unroll
                for (int mt = 0; mt < 2; mt++) {
                    mma_f16(acc[mt][nt], Al[mt][0], Al[mt][1], Al[mt][2],
                            Al[mt][3], bh0, bh1);
                    mma_f16(acc[mt][nt], Ah[mt][0], Ah[mt][1], Ah[mt][2],
                            Ah[mt][3], bl0, bl1);
                    mma_f16(acc[mt][nt], Ah[mt][0], Ah[mt][1], Ah[mt][2],
                            Ah[mt][3], bh0, bh1);
                }
            }
        }
        __syncthreads();
    }

#pragma unroll
    for (int mt = 0; mt < 2; mt++) {
        const int row0 = bm + wm * 32 + mt * 16 + g;
        const int row1 = row0 + 8;
        float s0a[4], s1a[4], d0a[4], d1a[4];
#pragma unroll
        for (int nt = 0; nt < 4; nt++) {
            const int h = wn * 4 + nt;
            const int colh = h * 4 + tig;
            float4 a = acc[mt][nt];
            if (row0 < N)
                g_xlh[(size_t)row0 * 32 + colh] = __floats2half2_rn(a.x, a.y);
            if (row1 < N)
                g_xlh[(size_t)row1 * 32 + colh] = __floats2half2_rn(a.z, a.w);

            float2 asv = make_float2(__ldg(att_s + h * 8 + 2 * tig),
                                     __ldg(att_s + h * 8 + 2 * tig + 1));
            float2 adv = make_float2(__ldg(att_d + h * 8 + 2 * tig),
                                     __ldg(att_d + h * 8 + 2 * tig + 1));
            float s0 = a.x * asv.x + a.y * asv.y;
            float s1 = a.z * asv.x + a.w * asv.y;
            float d0 = a.x * adv.x + a.y * adv.y;
            float d1 = a.z * adv.x + a.w * adv.y;
#pragma unroll
            for (int off = 1; off < 4; off <<= 1) {
                s0 += __shfl_xor_sync(0xffffffffu, s0, off);
                s1 += __shfl_xor_sync(0xffffffffu, s1, off);
                d0 += __shfl_xor_sync(0xffffffffu, d0, off);
                d1 += __shfl_xor_sync(0xffffffffu, d1, off);
            }
            s0a[nt] = s0; s1a[nt] = s1; d0a[nt] = d0; d1a[nt] = d1;
        }
        if (tig == 0) {
            if (row0 < N) {
                *(float4*)&g_as1[row0 * 8 + wn * 4] =
                    make_float4(s0a[0], s0a[1], s0a[2], s0a[3]);
                *(float4*)&g_ad1[row0 * 8 + wn * 4] =
                    make_float4(d0a[0], d0a[1], d0a[2], d0a[3]);
            }
            if (row1 < N) {
                *(float4*)&g_as1[row1 * 8 + wn * 4] =
                    make_float4(s1a[0], s1a[1], s1a[2], s1a[3]);
                *(float4*)&g_ad1[row1 * 8 + wn * 4] =
                    make_float4(d1a[0], d1a[1], d1a[2], d1a[3]);
            }
        }
    }
}

// ---- layer1 aggregation + bias + layer2 GEMM + layer2 logits (fused) ------
__global__ __launch_bounds__(256) void k_agg1(const float* __restrict__ b1,
                                              const float* __restrict__ W2,
                                              const float* __restrict__ atts2,
                                              const float* __restrict__ attd2,
                                              int N) {
    __shared__ float sh[8][64];
    int warp = (blockIdx.x * blockDim.x + threadIdx.x) >> 5;
    int wl = (threadIdx.x >> 5);
    int lane = threadIdx.x & 31;
    if (warp >= N) return;
    const int d = warp;
    const int h = lane >> 2;
    const float ad = g_ad1[d * 8 + h];

    float w = __expf(leaky02(g_as1[d * 8 + h] + ad));
    float2 v = __half22float2(g_xlh[(size_t)d * 32 + lane]);
    float nx = w * v.x, ny = w * v.y;
    float den = ((lane & 3) == 0) ? w : 0.f;

    const int e1 = g_rptr[d + 1];
#pragma unroll 4
    for (int e = g_rptr[d]; e < e1; e++) {
        int s = g_col[e];
        float we = __expf(leaky02(g_as1[s * 8 + h] + ad));
        float2 xs = __half22float2(g_xlh[(size_t)s * 32 + lane]);
        nx += we * xs.x;
        ny += we * xs.y;
        if ((lane & 3) == 0) den += we;
    }
    float dfull = __shfl_sync(0xffffffffu, den, lane & ~3) + 1e-16f;
    float inv = 1.f / dfull;

    sh[wl][lane * 2]     = nx * inv + __ldg(b1 + lane * 2);
    sh[wl][lane * 2 + 1] = ny * inv + __ldg(b1 + lane * 2 + 1);
    __syncwarp();

    const int c = lane & 15;
    const int jb = (lane >> 4) * 32;
    float y = 0.f;
#pragma unroll
    for (int j2 = 0; j2 < 32; j2++) {
        int j = jb + j2;
        y += sh[wl][j] * __ldg(W2 + j * 16 + c);
    }
    y += __shfl_xor_sync(0xffffffffu, y, 16);

    if (lane < 16) g_hl2[(size_t)d * 16 + c] = y;

    float pa = y * __ldg(atts2 + c);
    float pd = y * __ldg(attd2 + c);
#pragma unroll
    for (int off = 8; off >= 1; off >>= 1) {
        pa += __shfl_xor_sync(0xffffffffu, pa, off);
        pd += __shfl_xor_sync(0xffffffffu, pd, off);
    }
    if (lane == 0) {
        g_as2[d] = pa;
        g_ad2[d] = pd;
    }
}

// ------ layer2 aggregation + bias + elu + log_softmax (16 lanes/node) ------
__global__ __launch_bounds__(256) void k_agg2(const float* __restrict__ b2,
                                              float* __restrict__ out, int N) {
    int gid = (blockIdx.x * blockDim.x + threadIdx.x) >> 4;
    int c = threadIdx.x & 15;
    bool valid = gid < N;
    const int d = valid ? gid : 0;
    const float ad = g_ad2[d];

    float w = __expf(leaky02(g_as2[d] + ad));
    float num = w * g_hl2[(size_t)d * 16 + c];
    float den = w;

    const int e1 = g_rptr[d + 1];
#pragma unroll 4
    for (int e = g_rptr[d]; e < e1; e++) {
        int s = g_col[e];
        float we = __expf(leaky02(g_as2[s] + ad));
        num += we * g_hl2[(size_t)s * 16 + c];
        den += we;
    }
    float x = num / (den + 1e-16f) + __ldg(b2 + c);
    x = (x > 0.f) ? x : (__expf(x) - 1.f);

    float m = x;
#pragma unroll
    for (int off = 1; off < 16; off <<= 1)
        m = fmaxf(m, __shfl_xor_sync(0xffffffffu, m, off));
    float ssum = __expf(x - m);
#pragma unroll
    for (int off = 1; off < 16; off <<= 1)
        ssum += __shfl_xor_sync(0xffffffffu, ssum, off);
    if (valid) out[(size_t)d * 16 + c] = x - m - __logf(ssum);
}

// ---------------------------------------------------------------------------
extern "C" void kernel_launch(void* const* d_in, const int* in_sizes, int n_in,
                              void* d_out, int out_size) {
    const float* x     = (const float*)d_in[0];
    const int*   ei    = (const int*)d_in[1];
    const float* W1    = (const float*)d_in[2];
    const float* atts1 = (const float*)d_in[3];
    const float* attd1 = (const float*)d_in[4];
    const float* b1    = (const float*)d_in[5];
    const float* W2    = (const float*)d_in[6];
    const float* atts2 = (const float*)d_in[7];
    const float* attd2 = (const float*)d_in[8];
    const float* b2    = (const float*)d_in[9];
    float* out = (float*)d_out;

    const int N = in_sizes[0] / 512;
    const int E = in_sizes[1] / 2;
    const int ntiles = (N + 1023) >> 10;

    static cudaStream_t s_csr = nullptr;
    static cudaEvent_t ev_fork = nullptr, ev_join = nullptr;
    if (!s_csr) {
        cudaStreamCreateWithFlags(&s_csr, cudaStreamNonBlocking);
        cudaEventCreateWithFlags(&ev_fork, cudaEventDisableTiming);
        cudaEventCreateWithFlags(&ev_join, cudaEventDisableTiming);
    }

    // fork: CSR build on s_csr, GEMM1 on the main stream
    cudaEventRecord(ev_fork, 0);
    cudaStreamWaitEvent(s_csr, ev_fork, 0);

    k_hist<<<(E / 4 + 255) / 256, 256, 0, s_csr>>>(ei, E);
    k_scan1<<<ntiles, 1024, 0, s_csr>>>(N);
    k_scan3<<<(N + 255) / 256, 256, 0, s_csr>>>(N, E, ntiles);
    k_scatter<<<(E / 4 + 255) / 256, 256, 0, s_csr>>>(ei, E, N);
    cudaEventRecord(ev_join, s_csr);

    k_gemm1<<<(N + 127) / 128, 256>>>(x, W1, atts1, attd1, N);

    // join: aggregation needs both CSR and GEMM1
    cudaStreamWaitEvent(0, ev_join, 0);

    k_agg1<<<(N * 32 + 255) / 256, 256>>>(b1, W2, atts2, attd2, N);
    k_agg2<<<(N * 16 + 255) / 256, 256>>>(b2, out, N);
}